// round 3
// baseline (speedup 1.0000x reference)
#include <cuda_runtime.h>

// quadLayer: out[b,h,w, c*512 + a*32 + f] =
//   sum_m p[a][m] * W1[c][m][f] + sum_{m1,m2} p[a][m1]*p[a][m2] * W2[c][m1*4+m2][f]
// where p[a][mm] = x[b, 2h+((a>>2)>>1), 2w+((a>>2)&1), 4*(a&3)+mm]  (one float4 of x).
//
// R3: 4 c-planes per thread (halves LDS wavefronts per FFMA2 vs R2 again).
// 256 threads = 2 pixel-parities x 4 c-groups x 32 f. Features packed by
// a-parity in SMEM so ld.shared.v2.u64 yields {feat[2ap][k], feat[2ap+1][k]};
// weights duplicated into f32x2 regs; 8 independent accumulator chains.

#define NPIX 16
#define THREADS 256

__device__ __forceinline__ unsigned long long pack2(float lo, float hi) {
    unsigned long long r;
    asm("mov.b64 %0, {%1,%2};" : "=l"(r) : "f"(lo), "f"(hi));
    return r;
}

__device__ __forceinline__ void fma2(unsigned long long &d,
                                     unsigned long long a,
                                     unsigned long long b) {
    asm("fma.rn.f32x2 %0, %1, %2, %0;" : "+l"(d) : "l"(a), "l"(b));
}

__device__ __forceinline__ unsigned long long add2(unsigned long long a,
                                                   unsigned long long b) {
    unsigned long long r;
    asm("add.rn.f32x2 %0, %1, %2;" : "=l"(r) : "l"(a), "l"(b));
    return r;
}

__global__ void __launch_bounds__(THREADS, 1)
quad_kernel(const float* __restrict__ x,
            const float* __restrict__ W1,
            const float* __restrict__ W2,
            float* __restrict__ out)
{
    // feat[pix][ap][k][apar]: NPIX * 8 * 20 * 2 floats = 20 KB
    __shared__ __align__(16) float feat[NPIX * 8 * 20 * 2];

    const int t      = threadIdx.x;
    const int pixpar = t >> 7;        // 0..1 : which half of the pixels
    const int c0     = (t >> 5) & 3;  // 0..3 : c-planes c0, c0+4, c0+8, c0+12
    const int f      = t & 31;        // 0..31

    // ---- per-thread weights for 4 c-planes, duplicated into f32x2 ----
    unsigned long long wpA[20], wpB[20], wpC[20], wpD[20];
    {
        const int cA = c0, cB = c0 + 4, cC = c0 + 8, cD = c0 + 12;
#pragma unroll
        for (int m = 0; m < 4; m++) {
            float a = W1[cA * 128 + m * 32 + f];
            float b = W1[cB * 128 + m * 32 + f];
            float cc = W1[cC * 128 + m * 32 + f];
            float d = W1[cD * 128 + m * 32 + f];
            wpA[m] = pack2(a, a); wpB[m] = pack2(b, b);
            wpC[m] = pack2(cc, cc); wpD[m] = pack2(d, d);
        }
#pragma unroll
        for (int q = 0; q < 16; q++) {
            float a = W2[cA * 512 + q * 32 + f];
            float b = W2[cB * 512 + q * 32 + f];
            float cc = W2[cC * 512 + q * 32 + f];
            float d = W2[cD * 512 + q * 32 + f];
            wpA[4 + q] = pack2(a, a); wpB[4 + q] = pack2(b, b);
            wpC[4 + q] = pack2(cc, cc); wpD[4 + q] = pack2(d, d);
        }
    }

    // ---- feature build: one thread per (pix, a); 256 threads = NPIX*16 ----
    {
        const int pix = t >> 4;
        const int a   = t & 15;
        const int g   = blockIdx.x * NPIX + pix;          // global pixel id
        const int b   = g >> 10;
        const int h   = (g >> 5) & 31;
        const int wc  = g & 31;
        const int m   = a >> 2;
        const int i   = m >> 1;
        const int j   = m & 1;
        const int ch0 = (a & 3) * 4;
        const float4 v = *reinterpret_cast<const float4*>(
            x + (((b * 64 + 2 * h + i) * 64) + (2 * wc + j)) * 16 + ch0);
        const float p[4] = {v.x, v.y, v.z, v.w};
        float* fb = &feat[((pix * 8 + (a >> 1)) * 20) * 2 + (a & 1)];
#pragma unroll
        for (int k = 0; k < 4; k++) fb[2 * k] = p[k];
#pragma unroll
        for (int m1 = 0; m1 < 4; m1++)
#pragma unroll
            for (int m2 = 0; m2 < 4; m2++)
                fb[2 * (4 + m1 * 4 + m2)] = p[m1] * p[m2];
    }
    __syncthreads();

    const size_t gbase = (size_t)blockIdx.x * NPIX * 8192 + (size_t)f;
    const int offA = c0 * 512;
    const int offB = (c0 + 4) * 512;
    const int offC = (c0 + 8) * 512;
    const int offD = (c0 + 12) * 512;
    const unsigned int sbase = (unsigned int)__cvta_generic_to_shared(feat);

#pragma unroll 1
    for (int pp = 0; pp < NPIX / 2; pp++) {
        const int pix = 2 * pp + pixpar;
        const size_t obase = gbase + (size_t)pix * 8192;
        const unsigned int pbase = sbase + pix * (8 * 160);
#pragma unroll
        for (int ap = 0; ap < 8; ap++) {
            const unsigned int addr = pbase + ap * 160;   // 20 pairs * 8B
            unsigned long long aA0 = 0, aA1 = 0, aB0 = 0, aB1 = 0;
            unsigned long long aC0 = 0, aC1 = 0, aD0 = 0, aD1 = 0;
#pragma unroll
            for (int kk = 0; kk < 5; kk++) {
                unsigned long long p0, p1, p2, p3;
                asm("ld.shared.v2.u64 {%0,%1}, [%2];"
                    : "=l"(p0), "=l"(p1) : "r"(addr + kk * 32));
                asm("ld.shared.v2.u64 {%0,%1}, [%2];"
                    : "=l"(p2), "=l"(p3) : "r"(addr + kk * 32 + 16));
                fma2(aA0, wpA[4 * kk + 0], p0);
                fma2(aB0, wpB[4 * kk + 0], p0);
                fma2(aC0, wpC[4 * kk + 0], p0);
                fma2(aD0, wpD[4 * kk + 0], p0);
                fma2(aA1, wpA[4 * kk + 1], p1);
                fma2(aB1, wpB[4 * kk + 1], p1);
                fma2(aC1, wpC[4 * kk + 1], p1);
                fma2(aD1, wpD[4 * kk + 1], p1);
                fma2(aA0, wpA[4 * kk + 2], p2);
                fma2(aB0, wpB[4 * kk + 2], p2);
                fma2(aC0, wpC[4 * kk + 2], p2);
                fma2(aD0, wpD[4 * kk + 2], p2);
                fma2(aA1, wpA[4 * kk + 3], p3);
                fma2(aB1, wpB[4 * kk + 3], p3);
                fma2(aC1, wpC[4 * kk + 3], p3);
                fma2(aD1, wpD[4 * kk + 3], p3);
            }
            const unsigned long long aA = add2(aA0, aA1);
            const unsigned long long aB = add2(aB0, aB1);
            const unsigned long long aC = add2(aC0, aC1);
            const unsigned long long aD = add2(aD0, aD1);
            float l, h;
            asm("mov.b64 {%0,%1}, %2;" : "=f"(l), "=f"(h) : "l"(aA));
            out[obase + (size_t)(offA + (2 * ap) * 32)]     = l;
            out[obase + (size_t)(offA + (2 * ap + 1) * 32)] = h;
            asm("mov.b64 {%0,%1}, %2;" : "=f"(l), "=f"(h) : "l"(aB));
            out[obase + (size_t)(offB + (2 * ap) * 32)]     = l;
            out[obase + (size_t)(offB + (2 * ap + 1) * 32)] = h;
            asm("mov.b64 {%0,%1}, %2;" : "=f"(l), "=f"(h) : "l"(aC));
            out[obase + (size_t)(offC + (2 * ap) * 32)]     = l;
            out[obase + (size_t)(offC + (2 * ap + 1) * 32)] = h;
            asm("mov.b64 {%0,%1}, %2;" : "=f"(l), "=f"(h) : "l"(aD));
            out[obase + (size_t)(offD + (2 * ap) * 32)]     = l;
            out[obase + (size_t)(offD + (2 * ap + 1) * 32)] = h;
        }
    }
}

extern "C" void kernel_launch(void* const* d_in, const int* in_sizes, int n_in,
                              void* d_out, int out_size) {
    const float* x  = (const float*)d_in[0];
    const float* W1 = (const float*)d_in[1];
    const float* W2 = (const float*)d_in[2];
    float* out = (float*)d_out;
    quad_kernel<<<8192 / NPIX, THREADS>>>(x, W1, W2, out);
}

// round 4
// speedup vs baseline: 1.6521x; 1.6521x over previous
#include <cuda_runtime.h>

// quadLayer: out[b,h,w, c*512 + a*32 + f] =
//   sum_m p[a][m] W1[c][m][f] + sum_{m1,m2} p[a][m1] p[a][m2] W2[c][m1*4+m2][f]
// p[a][mm] = x[b, 2h+((a>>2)>>1), 2w+((a>>2)&1), 4*(a&3)+mm]  (one float4 of x).
//
// R4: symmetrized quadratic form -> 14 features per a instead of 20:
//   k 0..3  : p[m]              (weight W1[m])
//   k 4..7  : p[m]^2            (weight W2[5m])
//   k 8..13 : p[m1]p[m2], m1<m2 (weight W2[m1*4+m2] + W2[m2*4+m1])
// 2 c-planes per thread (R2 shape); features packed by a-parity in SMEM so
// ld.shared.v2.u64 yields {feat[2ap][k], feat[2ap+1][k]}; f32x2 throughout.

#define NPIX 16
#define THREADS 256
#define NK 14
#define APBYTES (NK * 8)   // 112 B per (pix, a-pair)

__device__ __forceinline__ unsigned long long pack2(float lo, float hi) {
    unsigned long long r;
    asm("mov.b64 %0, {%1,%2};" : "=l"(r) : "f"(lo), "f"(hi));
    return r;
}

__device__ __forceinline__ void fma2(unsigned long long &d,
                                     unsigned long long a,
                                     unsigned long long b) {
    asm("fma.rn.f32x2 %0, %1, %2, %0;" : "+l"(d) : "l"(a), "l"(b));
}

__device__ __forceinline__ unsigned long long add2(unsigned long long a,
                                                   unsigned long long b) {
    unsigned long long r;
    asm("add.rn.f32x2 %0, %1, %2;" : "=l"(r) : "l"(a), "l"(b));
    return r;
}

__global__ void __launch_bounds__(THREADS, 2)
quad_kernel(const float* __restrict__ x,
            const float* __restrict__ W1,
            const float* __restrict__ W2,
            float* __restrict__ out)
{
    // NPIX * 8 a-pairs * 14 k * 2 floats = 14 KB
    __shared__ __align__(16) float feat[NPIX * 8 * NK * 2];

    const int t  = threadIdx.x;
    const int c0 = t >> 5;   // 0..7  (handles c0 and c0+8)
    const int f  = t & 31;   // 0..31

    // ---- symmetrized per-thread weights for 2 c-planes ----
    unsigned long long wpA[NK], wpB[NK];
    {
        const int cA = c0, cB = c0 + 8;
#pragma unroll
        for (int m = 0; m < 4; m++) {              // linear
            float a = W1[cA * 128 + m * 32 + f];
            float b = W1[cB * 128 + m * 32 + f];
            wpA[m] = pack2(a, a);
            wpB[m] = pack2(b, b);
        }
#pragma unroll
        for (int m = 0; m < 4; m++) {              // squares (diag q = 5m)
            float a = W2[cA * 512 + (5 * m) * 32 + f];
            float b = W2[cB * 512 + (5 * m) * 32 + f];
            wpA[4 + m] = pack2(a, a);
            wpB[4 + m] = pack2(b, b);
        }
        int k = 8;                                  // cross terms, m1 < m2
#pragma unroll
        for (int m1 = 0; m1 < 4; m1++)
#pragma unroll
            for (int m2 = m1 + 1; m2 < 4; m2++) {
                float a = W2[cA * 512 + (m1 * 4 + m2) * 32 + f]
                        + W2[cA * 512 + (m2 * 4 + m1) * 32 + f];
                float b = W2[cB * 512 + (m1 * 4 + m2) * 32 + f]
                        + W2[cB * 512 + (m2 * 4 + m1) * 32 + f];
                wpA[k] = pack2(a, a);
                wpB[k] = pack2(b, b);
                k++;
            }
    }

    // ---- feature build: one thread per (pix, a); 256 threads = NPIX*16 ----
    {
        const int pix = t >> 4;
        const int a   = t & 15;
        const int g   = blockIdx.x * NPIX + pix;   // global pixel id
        const int b   = g >> 10;
        const int h   = (g >> 5) & 31;
        const int wc  = g & 31;
        const int m   = a >> 2;
        const int i   = m >> 1;
        const int j   = m & 1;
        const int ch0 = (a & 3) * 4;
        const float4 v = *reinterpret_cast<const float4*>(
            x + (((b * 64 + 2 * h + i) * 64) + (2 * wc + j)) * 16 + ch0);
        const float p[4] = {v.x, v.y, v.z, v.w};
        float* fb = &feat[(pix * 8 + (a >> 1)) * (NK * 2) + (a & 1)];
#pragma unroll
        for (int k = 0; k < 4; k++) fb[2 * k] = p[k];            // linear
#pragma unroll
        for (int m0 = 0; m0 < 4; m0++) fb[2 * (4 + m0)] = p[m0] * p[m0];
        int k = 8;
#pragma unroll
        for (int m1 = 0; m1 < 4; m1++)
#pragma unroll
            for (int m2 = m1 + 1; m2 < 4; m2++) {
                fb[2 * k] = p[m1] * p[m2];
                k++;
            }
    }
    __syncthreads();

    const size_t gbase = (size_t)blockIdx.x * NPIX * 8192 + (size_t)f;
    const int offA = c0 * 512;
    const int offB = (c0 + 8) * 512;
    const unsigned int sbase = (unsigned int)__cvta_generic_to_shared(feat);

#pragma unroll 1
    for (int pix = 0; pix < NPIX; pix++) {
        const size_t obase = gbase + (size_t)pix * 8192;
        const unsigned int pbase = sbase + pix * (8 * APBYTES);
#pragma unroll
        for (int ap = 0; ap < 8; ap++) {
            const unsigned int addr = pbase + ap * APBYTES;  // 14 pairs * 8B
            unsigned long long aA0 = 0, aA1 = 0, aB0 = 0, aB1 = 0;
            // 7 LDS.128 -> 14 feature pairs
            unsigned long long fp[NK];
#pragma unroll
            for (int q = 0; q < 7; q++) {
                asm("ld.shared.v2.u64 {%0,%1}, [%2];"
                    : "=l"(fp[2 * q]), "=l"(fp[2 * q + 1]) : "r"(addr + q * 16));
            }
#pragma unroll
            for (int k = 0; k < NK; k += 2) {
                fma2(aA0, wpA[k],     fp[k]);
                fma2(aB0, wpB[k],     fp[k]);
                fma2(aA1, wpA[k + 1], fp[k + 1]);
                fma2(aB1, wpB[k + 1], fp[k + 1]);
            }
            const unsigned long long aA = add2(aA0, aA1);
            const unsigned long long aB = add2(aB0, aB1);
            float lA, hA, lB, hB;
            asm("mov.b64 {%0,%1}, %2;" : "=f"(lA), "=f"(hA) : "l"(aA));
            asm("mov.b64 {%0,%1}, %2;" : "=f"(lB), "=f"(hB) : "l"(aB));
            out[obase + (size_t)(offA + (2 * ap) * 32)]     = lA;
            out[obase + (size_t)(offA + (2 * ap + 1) * 32)] = hA;
            out[obase + (size_t)(offB + (2 * ap) * 32)]     = lB;
            out[obase + (size_t)(offB + (2 * ap + 1) * 32)] = hB;
        }
    }
}

extern "C" void kernel_launch(void* const* d_in, const int* in_sizes, int n_in,
                              void* d_out, int out_size) {
    const float* x  = (const float*)d_in[0];
    const float* W1 = (const float*)d_in[1];
    const float* W2 = (const float*)d_in[2];
    float* out = (float*)d_out;
    quad_kernel<<<8192 / NPIX, THREADS>>>(x, W1, W2, out);
}